// round 2
// baseline (speedup 1.0000x reference)
#include <cuda_runtime.h>
#include <cuda_fp16.h>
#include <cstdint>
#include <cstddef>

#define NN 4096
#define HH 64
#define EE 10
#define NC 192   // 3*H

// ---------------- scratch (device globals; no allocations allowed) ----------------
__device__ __half g_edge16[(size_t)EE * NN * NN];   // 335 MB, edge * 4096 in fp16
__device__ __half g_h16[NN * HH];                   // current hidden in fp16
__device__ __half g_act16[(size_t)EE * NN * HH];    // per-edge aggregated messages
__device__ __half g_W16[EE * HH * NC];              // wz_wr_wh in fp16
__device__ __half g_uzurpad16[HH * NC];             // [uz|ur|0] padded to 192 cols
__device__ __half g_uh16[HH * HH];                  // uh in fp16
__device__ float  g_T0[NN * NC];                    // E * (input @ input_wzrh)
__device__ float  g_S[NN * NC];                     // gate pre-activations

// ---------------- PTX helpers ----------------
__device__ __forceinline__ void cp16(void* s, const void* g) {
    unsigned sa = (unsigned)__cvta_generic_to_shared(s);
    asm volatile("cp.async.cg.shared.global [%0], [%1], 16;" :: "r"(sa), "l"(g));
}
__device__ __forceinline__ void cp_commit() { asm volatile("cp.async.commit_group;"); }
template <int N_>
__device__ __forceinline__ void cp_wait() { asm volatile("cp.async.wait_group %0;" :: "n"(N_)); }

// trans ldmatrix: for operands stored [k][major] — produces logical transpose fragments
__device__ __forceinline__ void ldsm4t(unsigned& r0, unsigned& r1, unsigned& r2, unsigned& r3,
                                       const void* p) {
    unsigned a = (unsigned)__cvta_generic_to_shared(p);
    asm volatile("ldmatrix.sync.aligned.m8n8.x4.trans.shared.b16 {%0,%1,%2,%3}, [%4];"
                 : "=r"(r0), "=r"(r1), "=r"(r2), "=r"(r3) : "r"(a));
}
// non-trans ldmatrix: for A stored row-major [m][k]
__device__ __forceinline__ void ldsm4(unsigned& r0, unsigned& r1, unsigned& r2, unsigned& r3,
                                      const void* p) {
    unsigned a = (unsigned)__cvta_generic_to_shared(p);
    asm volatile("ldmatrix.sync.aligned.m8n8.x4.shared.b16 {%0,%1,%2,%3}, [%4];"
                 : "=r"(r0), "=r"(r1), "=r"(r2), "=r"(r3) : "r"(a));
}
__device__ __forceinline__ void mma16816(float* c, const unsigned* a, const unsigned* b) {
    asm volatile(
        "mma.sync.aligned.m16n8k16.row.col.f32.f16.f16.f32 "
        "{%0,%1,%2,%3},{%4,%5,%6,%7},{%8,%9},{%0,%1,%2,%3};"
        : "+f"(c[0]), "+f"(c[1]), "+f"(c[2]), "+f"(c[3])
        : "r"(a[0]), "r"(a[1]), "r"(a[2]), "r"(a[3]), "r"(b[0]), "r"(b[1]));
}

__device__ __forceinline__ float sigm(float x) { return 1.0f / (1.0f + __expf(-x)); }
__device__ __forceinline__ float tanh_fast(float x) { return 2.0f / (1.0f + __expf(-2.0f * x)) - 1.0f; }

// ---------------- setup kernels ----------------
// edge fp32 -> fp16 scaled by 4096 (avoids fp16 subnormals; values land in [0,1))
__global__ void k_conv_edge(const float* __restrict__ edge) {
    const size_t n4 = (size_t)EE * NN * NN / 4;
    const float4* src = (const float4*)edge;
    __half2* dst = (__half2*)g_edge16;
    for (size_t i = (size_t)blockIdx.x * blockDim.x + threadIdx.x; i < n4;
         i += (size_t)gridDim.x * blockDim.x) {
        float4 v = src[i];
        dst[2 * i]     = __floats2half2_rn(v.x * 4096.0f, v.y * 4096.0f);
        dst[2 * i + 1] = __floats2half2_rn(v.z * 4096.0f, v.w * 4096.0f);
    }
}

__global__ void k_setup(const float* __restrict__ hidden, const float* __restrict__ W,
                        const float* __restrict__ uzur, const float* __restrict__ uh,
                        float* __restrict__ dout) {
    int i = blockIdx.x * blockDim.x + threadIdx.x;   // grid covers 262144
    if (i < NN * HH) { float v = hidden[i]; dout[i] = v; g_h16[i] = __float2half_rn(v); }
    if (i < EE * HH * NC) g_W16[i] = __float2half_rn(W[i]);
    if (i < HH * NC) {
        int r = i / NC, c = i % NC;
        g_uzurpad16[i] = __float2half_rn(c < 2 * HH ? uzur[r * 2 * HH + c] : 0.0f);
    }
    if (i < HH * HH) g_uh16[i] = __float2half_rn(uh[i]);
}

// T0 = E * (input @ input_wzrh), loop-invariant
__global__ void k_t0(const float* __restrict__ input, const float* __restrict__ iwzrh) {
    __shared__ float xs[HH];
    int row = blockIdx.x;
    int j = threadIdx.x;  // 0..191
    if (j < HH) xs[j] = input[row * HH + j];
    __syncthreads();
    float acc = 0.0f;
#pragma unroll 8
    for (int i = 0; i < HH; i++) acc += xs[i] * iwzrh[i * NC + j];
    g_T0[row * NC + j] = (float)EE * acc;
}

// ---------------- GEMM1: act16[e] = edge[e]^T @ h + ba  (fp16 mma, fp32 accum) ----------------
__global__ __launch_bounds__(256) void k_gemm1(const int* __restrict__ d_it, int it,
                                               const float* __restrict__ ba) {
    if (it >= d_it[0]) return;
    const int e = blockIdx.y;
    const int m0 = blockIdx.x * 64;
    __shared__ __half As[2][64][72];   // A tile, [k][m] layout (edge is [k][m] row-major)
    __shared__ __half Bs[2][64][72];   // B tile, [k][n]
    const __half* Ae = g_edge16 + (size_t)e * NN * NN;
    const int tid = threadIdx.x;

    auto load = [&](int s, int kt) {
        const __half* ag = Ae + (size_t)(kt * 64) * NN + m0;
        const __half* bg = g_h16 + (kt * 64) * HH;
        for (int c = tid; c < 512; c += 256) {
            int row = c >> 3, ch = c & 7;
            cp16(&As[s][row][ch * 8], ag + (size_t)row * NN + ch * 8);
            cp16(&Bs[s][row][ch * 8], bg + row * HH + ch * 8);
        }
        cp_commit();
    };
    load(0, 0);

    const int w = tid >> 5, lane = tid & 31;
    const int m_base = (w >> 1) * 16;
    const int n_base = (w & 1) * 32;
    float acc[4][4];
#pragma unroll
    for (int t = 0; t < 4; t++) { acc[t][0] = acc[t][1] = acc[t][2] = acc[t][3] = 0.0f; }

    const int g = lane >> 3, r = lane & 7;
    const int a_k = ((g >> 1) & 1) * 8 + r;       // k-row within 16
    const int a_m = m_base + (g & 1) * 8;         // m-col within tile ([k][m] storage + trans)
    const int b_k = (g & 1) * 8 + r;
    const int b_n = (g >> 1) * 8;

    for (int kt = 0; kt < 64; kt++) {
        int cur = kt & 1;
        if (kt + 1 < 64) { load(cur ^ 1, kt + 1); cp_wait<1>(); } else { cp_wait<0>(); }
        __syncthreads();
#pragma unroll
        for (int kk = 0; kk < 4; kk++) {
            unsigned a[4];
            ldsm4t(a[0], a[1], a[2], a[3], &As[cur][kk * 16 + a_k][a_m]);
            unsigned b[8];
            ldsm4t(b[0], b[1], b[2], b[3], &Bs[cur][kk * 16 + b_k][n_base + 0 + b_n]);
            ldsm4t(b[4], b[5], b[6], b[7], &Bs[cur][kk * 16 + b_k][n_base + 16 + b_n]);
            mma16816(acc[0], a, b + 0);
            mma16816(acc[1], a, b + 2);
            mma16816(acc[2], a, b + 4);
            mma16816(acc[3], a, b + 6);
        }
        __syncthreads();
    }

    // epilogue: undo x4096 scaling, add ba, store fp16
    const float inv = 1.0f / 4096.0f;
    const int rrow = m0 + m_base + (lane >> 2);
    const int cbase = n_base + 2 * (lane & 3);
    __half2* actp = (__half2*)g_act16;
#pragma unroll
    for (int t = 0; t < 4; t++) {
        int n = cbase + t * 8;
        float b0 = ba[n], b1 = ba[n + 1];
        __half2 v0 = __floats2half2_rn(acc[t][0] * inv + b0, acc[t][1] * inv + b1);
        __half2 v1 = __floats2half2_rn(acc[t][2] * inv + b0, acc[t][3] * inv + b1);
        size_t base0 = ((size_t)e * NN + rrow) * HH + n;
        actp[base0 >> 1] = v0;
        actp[(base0 + 8 * HH) >> 1] = v1;
    }
}

// ---------------- Update: S = sum_e act16[e]@W16[e] + h16@[uz|ur|0]; then gates ----------------
__global__ __launch_bounds__(256) void k_update(const int* __restrict__ d_it, int it,
                                                float* __restrict__ hio) {
    if (it >= d_it[0]) return;
    const int m0 = blockIdx.x * 64;
    __shared__ __align__(16) unsigned char smem_raw[36864];
    __half (*As)[72]  = (__half(*)[72])smem_raw;             // 64*72*2  = 9216 B, [m][k] layout
    __half (*Bs)[200] = (__half(*)[200])(smem_raw + 9216);   // 64*200*2 = 25600 B, [k][n] layout

    const int tid = threadIdx.x, w = tid >> 5, lane = tid & 31;
    const int m_base = (w >> 1) * 16;
    const int n_base = (w & 1) * 96;
    float acc[12][4];
#pragma unroll
    for (int t = 0; t < 12; t++) { acc[t][0] = acc[t][1] = acc[t][2] = acc[t][3] = 0.0f; }

    const int g = lane >> 3, r = lane & 7;
    // A stored row-major [m][k]: NON-trans ldmatrix.
    //   a[0]=(m0-7,k0-7)  a[1]=(m8-15,k0-7)  a[2]=(m0-7,k8-15)  a[3]=(m8-15,k8-15)
    const int a_row = m_base + (g & 1) * 8 + r;   // m index within CTA tile
    const int a_col = ((g >> 1) & 1) * 8;         // k offset within 16-wide slab
    // B stored [k][n]: trans ldmatrix (same as gemm1)
    const int b_k = (g & 1) * 8 + r;
    const int b_nn = (g >> 1) * 8;

    for (int e = 0; e <= EE; e++) {   // e == EE is the virtual [uz|ur|0] edge with A = h16
        const __half* ag = (e < EE) ? g_act16 + ((size_t)e * NN + m0) * HH : g_h16 + m0 * HH;
        const __half* bg = (e < EE) ? g_W16 + e * HH * NC : g_uzurpad16;
        for (int c = tid; c < 512; c += 256) {
            int row = c >> 3, ch = c & 7;
            cp16(&As[row][ch * 8], ag + row * HH + ch * 8);
        }
        for (int c = tid; c < 1536; c += 256) {
            int row = c / 24, ch = c % 24;
            cp16(&Bs[row][ch * 8], bg + row * NC + ch * 8);
        }
        cp_commit(); cp_wait<0>();
        __syncthreads();
#pragma unroll
        for (int kk = 0; kk < 4; kk++) {
            unsigned a[4];
            ldsm4(a[0], a[1], a[2], a[3], &As[a_row][kk * 16 + a_col]);
#pragma unroll
            for (int p = 0; p < 6; p++) {
                unsigned b[4];
                ldsm4t(b[0], b[1], b[2], b[3], &Bs[kk * 16 + b_k][n_base + p * 16 + b_nn]);
                mma16816(acc[2 * p], a, b);
                mma16816(acc[2 * p + 1], a, b + 2);
            }
        }
        __syncthreads();
    }

    // write S tiles (fp32)
    {
        const int rrow = m0 + m_base + (lane >> 2);
        const int cb = n_base + 2 * (lane & 3);
        float2* sp = (float2*)g_S;
#pragma unroll
        for (int t = 0; t < 12; t++) {
            int n = cb + t * 8;
            sp[((size_t)rrow * NC + n) >> 1]       = make_float2(acc[t][0], acc[t][1]);
            sp[((size_t)(rrow + 8) * NC + n) >> 1] = make_float2(acc[t][2], acc[t][3]);
        }
    }
    __syncthreads();   // S visible CTA-wide; smem reusable

    // ---- phase B: row-local gates ----
    __half2* uh2 = (__half2*)smem_raw;                       // 8192 B
    float (*rh_sm)[64] = (float(*)[64])(smem_raw + 8192);    // 64*64*4 = 16384 B
    {
        const uint4* src = (const uint4*)g_uh16;   // 8192 B = 512 uint4
        uint4* dst = (uint4*)smem_raw;
        for (int c = tid; c < 512; c += 256) dst[c] = src[c];
    }
    __syncthreads();

    const int c0 = 2 * lane;        // this lane's two columns
    const int row0 = m0 + w * 8;    // this warp's 8 rows
    float zz0[8], zz1[8], hv0[8], hv1[8];
#pragma unroll
    for (int q = 0; q < 8; q++) {
        int row = row0 + q;
        float2 s_z = *(const float2*)&g_S[(size_t)row * NC + c0];
        float2 t_z = *(const float2*)&g_T0[(size_t)row * NC + c0];
        float2 s_r = *(const float2*)&g_S[(size_t)row * NC + HH + c0];
        float2 t_r = *(const float2*)&g_T0[(size_t)row * NC + HH + c0];
        float2 h2  = *(const float2*)&hio[(size_t)row * HH + c0];
        float z0 = sigm(s_z.x + t_z.x), z1 = sigm(s_z.y + t_z.y);
        float r0v = sigm(s_r.x + t_r.x), r1v = sigm(s_r.y + t_r.y);
        zz0[q] = z0; zz1[q] = z1; hv0[q] = h2.x; hv1[q] = h2.y;
        rh_sm[w * 8 + q][c0] = r0v * h2.x;
        rh_sm[w * 8 + q][c0 + 1] = r1v * h2.y;
    }
    __syncwarp();

    float u0[8], u1[8];
#pragma unroll
    for (int q = 0; q < 8; q++) { u0[q] = 0.0f; u1[q] = 0.0f; }
#pragma unroll 4
    for (int i = 0; i < HH; i++) {
        float2 wv = __half22float2(uh2[i * 32 + lane]);
#pragma unroll
        for (int q = 0; q < 8; q++) {
            float rhv = rh_sm[w * 8 + q][i];
            u0[q] += rhv * wv.x;
            u1[q] += rhv * wv.y;
        }
    }

    __half2* h16p = (__half2*)g_h16;
#pragma unroll
    for (int q = 0; q < 8; q++) {
        int row = row0 + q;
        float2 s_h = *(const float2*)&g_S[(size_t)row * NC + 2 * HH + c0];
        float2 t_h = *(const float2*)&g_T0[(size_t)row * NC + 2 * HH + c0];
        float ht0 = tanh_fast(s_h.x + t_h.x + u0[q]);
        float ht1 = tanh_fast(s_h.y + t_h.y + u1[q]);
        float hn0 = hv0[q] + zz0[q] * (ht0 - hv0[q]);
        float hn1 = hv1[q] + zz1[q] * (ht1 - hv1[q]);
        *(float2*)&hio[(size_t)row * HH + c0] = make_float2(hn0, hn1);
        h16p[((size_t)row * HH + c0) >> 1] = __floats2half2_rn(hn0, hn1);
    }
}

// ---------------- launch ----------------
extern "C" void kernel_launch(void* const* d_in, const int* in_sizes, int n_in,
                              void* d_out, int out_size) {
    const float* input  = (const float*)d_in[0];
    const float* hidden = (const float*)d_in[1];
    const float* edge   = (const float*)d_in[2];
    const float* ba     = (const float*)d_in[3];
    const float* W      = (const float*)d_in[4];
    const float* uzur   = (const float*)d_in[5];
    const float* uh     = (const float*)d_in[6];
    const float* iwzrh  = (const float*)d_in[7];
    const int*   d_it   = (const int*)d_in[8];
    float* out = (float*)d_out;

    k_conv_edge<<<8192, 256>>>(edge);
    k_setup<<<(NN * HH + 255) / 256, 256>>>(hidden, W, uzur, uh, out);
    k_t0<<<NN, NC>>>(input, iwzrh);

    for (int it = 0; it < 10; ++it) {
        k_gemm1<<<dim3(NN / 64, EE), 256>>>(d_it, it, ba);
        k_update<<<NN / 64, 256>>>(d_it, it, out);
    }
}